// round 15
// baseline (speedup 1.0000x reference)
#include <cuda_runtime.h>
#include <cuda_fp16.h>
#include <cstdint>
#include <math.h>

#define Nn 64
#define Kk 64
#define Dd 256
#define Ll 4096
#define NTILES 32
#define NT 512

// ---- smem byte offsets ----
#define XRAW_OFF 0        // raw x fp32 [256 d][68 p] (pitch 272B)
#define XH0_OFF  69632    // x fp16 [256 d][72 p] (pitch 144B), parity 0
#define XH1_OFF  106496   // parity 1
#define WH_OFF   143360   // W fp16 [64 k][264 d] (pitch 528B)
#define PA0_OFF  177152   // probs*ri fp16 [64 p][72 k] (pitch 144B), parity 0
#define PA1_OFF  186368   // parity 1
#define LS_OFF   195584   // logits [64 p][68 k] f32 (pitch 272B); reused for S2 staging
#define NRM_OFF  212992   // float[2][1024] partial sumsq (parity stride 1024)
#define RN_OFF   221184   // float[2][64]  ri = 1/||x||
#define NX_OFF   221696   // float[2][64]  ||x||
#define SMEM_TOTAL 222208

#define XHD (XH1_OFF - XH0_OFF)   // 36864
#define PAD (PA1_OFF - PA0_OFF)   // 9216

__device__ float g_S1p[2][Nn][Kk][Dd];
__device__ float g_S2p[2][Nn][Kk];

static __device__ __forceinline__ uint32_t smem_u32(const void* p) {
    uint32_t a;
    asm("{ .reg .u64 t; cvta.to.shared.u64 t, %1; cvt.u32.u64 %0, t; }" : "=r"(a) : "l"(p));
    return a;
}
static __device__ __forceinline__ void ldsm4(uint32_t r[4], uint32_t a) {
    asm volatile("ldmatrix.sync.aligned.m8n8.x4.shared.b16 {%0,%1,%2,%3}, [%4];"
                 : "=r"(r[0]), "=r"(r[1]), "=r"(r[2]), "=r"(r[3]) : "r"(a));
}
static __device__ __forceinline__ void ldsm4t(uint32_t r[4], uint32_t a) {
    asm volatile("ldmatrix.sync.aligned.m8n8.x4.trans.shared.b16 {%0,%1,%2,%3}, [%4];"
                 : "=r"(r[0]), "=r"(r[1]), "=r"(r[2]), "=r"(r[3]) : "r"(a));
}
static __device__ __forceinline__ void mma_f16(float c[4], const uint32_t a[4],
                                               uint32_t b0, uint32_t b1) {
    asm volatile(
        "mma.sync.aligned.m16n8k16.row.col.f32.f16.f16.f32 "
        "{%0,%1,%2,%3},{%4,%5,%6,%7},{%8,%9},{%0,%1,%2,%3};"
        : "+f"(c[0]), "+f"(c[1]), "+f"(c[2]), "+f"(c[3])
        : "r"(a[0]), "r"(a[1]), "r"(a[2]), "r"(a[3]), "r"(b0), "r"(b1));
}
#define BAR_SYNC(id, cnt)   asm volatile("bar.sync %0, %1;"   :: "r"(id), "r"(cnt) : "memory")
#define BAR_ARRIVE(id, cnt) asm volatile("bar.arrive %0, %1;" :: "r"(id), "r"(cnt) : "memory")
#define CP_ASYNC16(dst, src) \
    asm volatile("cp.async.cg.shared.global [%0], [%1], 16;" :: "r"(dst), "l"(src) : "memory")
#define CP_COMMIT()  asm volatile("cp.async.commit_group;" ::: "memory")
#define CP_WAIT0()   asm volatile("cp.async.wait_group 0;" ::: "memory")

// named barrier ids:
// 1 = G1 internal, 7 = G2 internal
// 2/3 = XHfree par0/1, 4/5 = XHready par0/1, 8/9 = PAready par0/1

__global__ void netvlad_noop() {}

__global__ __launch_bounds__(NT, 1)
void netvlad_mma(const float* __restrict__ x, const float* __restrict__ w) {
    extern __shared__ char sm[];
    const uint32_t sb = smem_u32(sm);
    const int tid = threadIdx.x;
    const int lane = tid & 31;
    const int n  = blockIdx.x >> 1;
    const int hf = blockIdx.x & 1;

    float* Lsp = (float*)(sm + LS_OFF);
    float* RN  = (float*)(sm + RN_OFF);

    // ---- load W fp16 [k][d] pitch 264 halves (all 512 threads) ----
    for (int i = tid; i < Kk * Dd; i += NT) {
        int k = i >> 8, d = i & 255;
        *(__half*)(sm + WH_OFF + k * 528 + 2 * d) = __float2half_rn(w[i]);
    }

    const float* xn = x + (size_t)n * Dd * Ll + (size_t)hf * 2048;

    // ---- G2 issues cp.async for tile 0 ----
    if (tid >= 256) {
        const int t2 = tid - 256;
#pragma unroll 4
        for (int i = 0; i < 16; ++i) {
            int c = t2 + 256 * i;
            int d = c >> 4, p4 = c & 15;
            uint32_t dst = sb + XRAW_OFF + d * 272 + p4 * 16;
            const float* src = xn + (size_t)d * Ll + p4 * 4;
            CP_ASYNC16(dst, src);
        }
        CP_COMMIT();
    }
    __syncthreads();

    if (tid < 256) {
        // ============ G1: norm-reduce + GEMM1 + softmax + S2 ============
        const int wv = tid >> 5;
        const int p0 = (wv >> 1) * 16;
        const int k0 = (wv & 1) * 32;
        const int g  = lane >> 2;
        const int tg = lane & 3;
        const int pp = tid >> 2;       // softmax pixel
        const int sg = tid & 3;        // softmax subgroup

        const uint32_t aA1b = sb + XH0_OFF +
            ((lane & 7) + ((lane >> 4) << 3)) * 144 + (p0 + ((lane >> 3) & 1) * 8) * 2;
        const uint32_t aB1 = sb + WH_OFF + (k0 + (lane & 15)) * 528 + ((lane >> 4) << 4);

        float s2p[16];                 // S2 partials: k = sg*16+j for pixel pp
#pragma unroll
        for (int j = 0; j < 16; ++j) s2p[j] = 0.0f;

        for (int t = 0; t < NTILES; ++t) {
            const int par = t & 1;
            BAR_SYNC(4 + par, NT);          // XH[par] + nrm[par] ready

            // norm reduction (warps 0,1): 1024 partials per parity
            if (tid < 64) {
                const float* nr = (const float*)(sm + NRM_OFF) + par * 1024;
                float q = 0.0f;
#pragma unroll
                for (int i = 0; i < 16; ++i) q += nr[i * 64 + tid];
                float nx = fmaxf(sqrtf(q), 1e-12f);
                ((float*)(sm + NX_OFF))[par * 64 + tid] = nx;
                RN[par * 64 + tid] = 1.0f / nx;
            }

            // GEMM1: logits_raw[p][k] = x^T W^T  (contraction d=256)
            {
                float l0[4] = {0, 0, 0, 0}, l1[4] = {0, 0, 0, 0};
                float l2[4] = {0, 0, 0, 0}, l3[4] = {0, 0, 0, 0};
                const uint32_t a1 = aA1b + (par ? XHD : 0);
#pragma unroll 4
                for (int ks = 0; ks < 16; ++ks) {
                    uint32_t A[4], B0[4], B1[4];
                    ldsm4t(A, a1 + ks * 2304);
                    ldsm4(B0, aB1 + ks * 32);
                    ldsm4(B1, aB1 + 16 * 528 + ks * 32);
                    mma_f16(l0, A, B0[0], B0[2]);
                    mma_f16(l1, A, B0[1], B0[3]);
                    mma_f16(l2, A, B1[0], B1[2]);
                    mma_f16(l3, A, B1[1], B1[3]);
                }
                int r0 = (p0 + g) * 68, r1 = (p0 + 8 + g) * 68;
                *(float2*)&Lsp[r0 + k0 + tg * 2]      = make_float2(l0[0], l0[1]);
                *(float2*)&Lsp[r1 + k0 + tg * 2]      = make_float2(l0[2], l0[3]);
                *(float2*)&Lsp[r0 + k0 + 8 + tg * 2]  = make_float2(l1[0], l1[1]);
                *(float2*)&Lsp[r1 + k0 + 8 + tg * 2]  = make_float2(l1[2], l1[3]);
                *(float2*)&Lsp[r0 + k0 + 16 + tg * 2] = make_float2(l2[0], l2[1]);
                *(float2*)&Lsp[r1 + k0 + 16 + tg * 2] = make_float2(l2[2], l2[3]);
                *(float2*)&Lsp[r0 + k0 + 24 + tg * 2] = make_float2(l3[0], l3[1]);
                *(float2*)&Lsp[r1 + k0 + 24 + tg * 2] = make_float2(l3[2], l3[3]);
            }
            BAR_ARRIVE(2 + par, NT);        // XH[par] reads done -> G2 may overwrite
            BAR_SYNC(1, 256);               // logits + RN visible within G1

            // softmax over k (4 threads per pixel), write probs*ri fp16; S2 in fp32
            {
                const float ri = RN[par * 64 + pp];
                const float* row = Lsp + pp * 68 + sg * 16;
                float e[16];
                float4 v0 = *(const float4*)(row + 0);
                float4 v1 = *(const float4*)(row + 4);
                float4 v2 = *(const float4*)(row + 8);
                float4 v3 = *(const float4*)(row + 12);
                e[0]=v0.x; e[1]=v0.y; e[2]=v0.z; e[3]=v0.w;
                e[4]=v1.x; e[5]=v1.y; e[6]=v1.z; e[7]=v1.w;
                e[8]=v2.x; e[9]=v2.y; e[10]=v2.z; e[11]=v2.w;
                e[12]=v3.x; e[13]=v3.y; e[14]=v3.z; e[15]=v3.w;
                float m = e[0];
#pragma unroll
                for (int j = 1; j < 16; ++j) m = fmaxf(m, e[j]);
                m = fmaxf(m, __shfl_xor_sync(0xffffffffu, m, 1));
                m = fmaxf(m, __shfl_xor_sync(0xffffffffu, m, 2));
                float ssum = 0.0f;
#pragma unroll
                for (int j = 0; j < 16; ++j) { e[j] = __expf(ri * (e[j] - m)); ssum += e[j]; }
                ssum += __shfl_xor_sync(0xffffffffu, ssum, 1);
                ssum += __shfl_xor_sync(0xffffffffu, ssum, 2);
                float invs = 1.0f / ssum;
                float sc = ri * invs;
                uint32_t hb[8];
#pragma unroll
                for (int j = 0; j < 8; ++j) {
                    __half2 hv = __floats2half2_rn(e[2 * j] * sc, e[2 * j + 1] * sc);
                    hb[j] = *(uint32_t*)&hv;
                }
                char* pd = sm + (par ? PA1_OFF : PA0_OFF) + pp * 144 + sg * 32;
                *(uint4*)pd        = make_uint4(hb[0], hb[1], hb[2], hb[3]);
                *(uint4*)(pd + 16) = make_uint4(hb[4], hb[5], hb[6], hb[7]);
                // S2 partial: probs = e * (1/ssum), exact fp32
#pragma unroll
                for (int j = 0; j < 16; ++j) s2p[j] += e[j] * invs;
            }
            BAR_ARRIVE(8 + par, NT);        // PA[par] ready
            // (no trailing barrier: next iteration's BAR_SYNC(4+par') orders
            //  all softmax Lsp reads before the next GEMM1's Lsp writes)
        }

        // ---- S2 final reduction (Lsp is dead; reuse as [64 k][68] staging) ----
        BAR_SYNC(1, 256);                   // all softmax Lsp reads done
#pragma unroll
        for (int j = 0; j < 16; ++j) Lsp[(sg * 16 + j) * 68 + pp] = s2p[j];
        BAR_SYNC(1, 256);
        if (tid < 64) {
            const float* rowk = Lsp + tid * 68;
            float s = 0.0f;
#pragma unroll 8
            for (int p2 = 0; p2 < 64; ++p2) s += rowk[p2];
            g_S2p[hf][n][tid] = s;
        }
    } else {
        // ============ G2: convert + cp.async + GEMM2 ============
        const int t2 = tid - 256;
        const int pq4  = t2 & 15;      // pixel quad: p = 4*pq4 .. +3
        const int dq16 = t2 >> 4;      // 0..15, d-range dq16*16..+15
        const int d0 = ((t2 >> 5) >> 1) * 64;
        const int kq = ((t2 >> 5) & 1) * 32;
        const int g  = lane >> 2;
        const int tg = lane & 3;

        const uint32_t aA2b = sb + XH0_OFF + (d0 + (lane & 15)) * 144 + ((lane >> 4) << 4);
        // B from PA [p][k] via ldsm.trans
        const uint32_t aB2b = sb + PA0_OFF +
            ((lane & 7) + ((lane >> 4) << 3)) * 144 + (kq + ((lane >> 3) & 1) * 8) * 2;

        float acc[4][4][4];
#pragma unroll
        for (int i = 0; i < 4; i++)
#pragma unroll
            for (int j = 0; j < 4; j++)
#pragma unroll
                for (int q = 0; q < 4; q++) acc[i][j][q] = 0.0f;

        for (int t = 0; t < NTILES; ++t) {
            const int par = t & 1;
            if (t >= 2) BAR_SYNC(2 + par, NT);   // XH[par] free
            CP_WAIT0();

            // convert XRAW -> fp16 XH[par]: 4 pixels x 16 d per thread
            {
                const char* srcb = sm + XRAW_OFF + pq4 * 16;
                char* dstb = sm + (par ? XH1_OFF : XH0_OFF) + pq4 * 8;
                float s0 = 0.0f, s1 = 0.0f, s2 = 0.0f, s3 = 0.0f;
#pragma unroll 8
                for (int j = 0; j < 16; ++j) {
                    int d = dq16 * 16 + j;
                    float4 v = *(const float4*)(srcb + d * 272);
                    s0 += v.x * v.x; s1 += v.y * v.y;
                    s2 += v.z * v.z; s3 += v.w * v.w;
                    __half2 h01 = __floats2half2_rn(v.x, v.y);
                    __half2 h23 = __floats2half2_rn(v.z, v.w);
                    *(uint2*)(dstb + d * 144) =
                        make_uint2(*(uint32_t*)&h01, *(uint32_t*)&h23);
                }
                float4* nr4 = (float4*)((float*)(sm + NRM_OFF) + par * 1024);
                nr4[dq16 * 16 + pq4] = make_float4(s0, s1, s2, s3);
            }
            BAR_SYNC(7, 256);                    // all XRAW reads done

            if (t + 1 < NTILES) {
#pragma unroll 4
                for (int i = 0; i < 16; ++i) {
                    int c = t2 + 256 * i;
                    int d = c >> 4, p4 = c & 15;
                    uint32_t dst = sb + XRAW_OFF + d * 272 + p4 * 16;
                    const float* src = xn + (size_t)d * Ll + (t + 1) * 64 + p4 * 4;
                    CP_ASYNC16(dst, src);
                }
                CP_COMMIT();
            }
            BAR_ARRIVE(4 + par, NT);             // XH[par] + nrm[par] ready

            if (t > 0) {
                const int q = par ^ 1;
                BAR_SYNC(8 + q, NT);             // PA[q] ready
                const uint32_t a2 = aA2b + (q ? XHD : 0);
                const uint32_t b2 = aB2b + (q ? PAD : 0);
#pragma unroll
                for (int ps = 0; ps < 4; ++ps) {
                    uint32_t B0[4], B1[4];
                    ldsm4t(B0, b2 + ps * 2304);
                    ldsm4t(B1, b2 + 32 + ps * 2304);
#pragma unroll
                    for (int i = 0; i < 4; ++i) {
                        uint32_t A[4];
                        ldsm4(A, a2 + i * 2304 + ps * 32);
                        mma_f16(acc[i][0], A, B0[0], B0[2]);
                        mma_f16(acc[i][1], A, B0[1], B0[3]);
                        mma_f16(acc[i][2], A, B1[0], B1[2]);
                        mma_f16(acc[i][3], A, B1[1], B1[3]);
                    }
                }
            }
        }

        // tail: GEMM2 for tile 31 (par 1)
        {
            BAR_SYNC(9, NT);
            const uint32_t a2 = aA2b + XHD;
            const uint32_t b2 = aB2b + PAD;
#pragma unroll
            for (int ps = 0; ps < 4; ++ps) {
                uint32_t B0[4], B1[4];
                ldsm4t(B0, b2 + ps * 2304);
                ldsm4t(B1, b2 + 32 + ps * 2304);
#pragma unroll
                for (int i = 0; i < 4; ++i) {
                    uint32_t A[4];
                    ldsm4(A, a2 + i * 2304 + ps * 32);
                    mma_f16(acc[i][0], A, B0[0], B0[2]);
                    mma_f16(acc[i][1], A, B0[1], B0[3]);
                    mma_f16(acc[i][2], A, B1[0], B1[2]);
                    mma_f16(acc[i][3], A, B1[1], B1[3]);
                }
            }
        }

        // stage acc into XRAW region (only G2 touches XRAW)
        float* stg = (float*)sm;   // [64 k][260 d] f32
#pragma unroll
        for (int i = 0; i < 4; ++i)
#pragma unroll
            for (int j = 0; j < 4; ++j) {
                int d  = d0 + 16 * i + g;
                int kk = kq + 8 * j + tg * 2;
                stg[kk * 260 + d]           = acc[i][j][0];
                stg[(kk + 1) * 260 + d]     = acc[i][j][1];
                stg[kk * 260 + d + 8]       = acc[i][j][2];
                stg[(kk + 1) * 260 + d + 8] = acc[i][j][3];
            }
    }

    __syncthreads();   // staging complete (S1 in XRAW region)
    {
        int k   = tid >> 3;
        int dq2 = (tid & 7) * 32;
        const float* stg = (const float*)sm;
#pragma unroll
        for (int jj = 0; jj < 8; ++jj) {
            float4 v = *(const float4*)&stg[k * 260 + dq2 + jj * 4];
            *(float4*)&g_S1p[hf][n][k][dq2 + jj * 4] = v;
        }
    }
}

__global__ __launch_bounds__(256)
void netvlad_finalize(const float* __restrict__ cent, float* __restrict__ out) {
    const int n = blockIdx.x;
    const int tid = threadIdx.x;
    const int w8 = tid >> 5, lane = tid & 31;
    __shared__ float s2s[64];
    __shared__ float wsum[8];
    __shared__ float ginv_s;

    if (tid < 64) s2s[tid] = g_S2p[0][n][tid] + g_S2p[1][n][tid];
    __syncthreads();

    float v[8][8];
    float gs = 0.0f;
#pragma unroll
    for (int kk = 0; kk < 8; ++kk) {
        int k = w8 * 8 + kk;
        float s2 = s2s[k];
        float loc = 0.0f;
#pragma unroll
        for (int j = 0; j < 8; ++j) {
            int d = j * 32 + lane;
            float a = g_S1p[0][n][k][d] + g_S1p[1][n][k][d] - s2 * cent[k * Dd + d];
            v[kk][j] = a;
            loc += a * a;
        }
#pragma unroll
        for (int o = 16; o > 0; o >>= 1) loc += __shfl_xor_sync(0xffffffffu, loc, o);
        float inv = 1.0f / fmaxf(sqrtf(loc), 1e-12f);
#pragma unroll
        for (int j = 0; j < 8; ++j) { v[kk][j] *= inv; gs += v[kk][j] * v[kk][j]; }
    }
#pragma unroll
    for (int o = 16; o > 0; o >>= 1) gs += __shfl_xor_sync(0xffffffffu, gs, o);
    if (lane == 0) wsum[w8] = gs;
    __syncthreads();
    if (tid == 0) {
        float t = 0.0f;
#pragma unroll
        for (int i = 0; i < 8; ++i) t += wsum[i];
        ginv_s = 1.0f / fmaxf(sqrtf(t), 1e-12f);
    }
    __syncthreads();
    float gi = ginv_s;
    size_t base = (size_t)n * Kk * Dd;
#pragma unroll
    for (int kk = 0; kk < 8; ++kk) {
        int k = w8 * 8 + kk;
#pragma unroll
        for (int j = 0; j < 8; ++j)
            out[base + (size_t)k * Dd + j * 32 + lane] = v[kk][j] * gi;
    }
}

extern "C" void kernel_launch(void* const* d_in, const int* in_sizes, int n_in,
                              void* d_out, int out_size) {
    const float* x = (const float*)d_in[0];
    const float* w = (const float*)d_in[1];
    const float* c = (const float*)d_in[2];
    float* out = (float*)d_out;

    cudaFuncSetAttribute(netvlad_mma,
                         cudaFuncAttributeMaxDynamicSharedMemorySize, SMEM_TOTAL);

    // 3-launch pattern keeps ncu (-s 5 -c 1) on netvlad_mma.
    netvlad_mma<<<2 * Nn, NT, SMEM_TOTAL>>>(x, w);
    netvlad_finalize<<<Nn, 256>>>(c, out);
    netvlad_noop<<<1, 32>>>();
}

// round 16
// speedup vs baseline: 1.5222x; 1.5222x over previous
#include <cuda_runtime.h>
#include <cuda_fp16.h>
#include <cstdint>
#include <math.h>

#define Nn 64
#define Kk 64
#define Dd 256
#define Ll 4096
#define NTILES 32
#define NT 512

// ---- smem byte offsets ----
#define XRAW_OFF 0        // raw x fp32 [256 d][68 p] (pitch 272B)
#define XH0_OFF  69632    // x fp16 [256 d][72 p] (pitch 144B), parity 0
#define XH1_OFF  106496   // parity 1
#define WH_OFF   143360   // W fp16 [64 k][264 d] (pitch 528B)
#define PA0_OFF  177152   // probs*ri fp16 [64 p][72 k] (pitch 144B), parity 0
#define PA1_OFF  186368   // parity 1
#define LS_OFF   195584   // logits [64 p][68 k] f32 (pitch 272B)
#define NRM_OFF  212992   // float[2][1024] partial sumsq (parity stride 1024)
#define RN_OFF   221184   // float[2][64]  ri = 1/||x||
#define NX_OFF   221696   // float[2][64]  ||x||
#define SMEM_TOTAL 222208

#define XHD (XH1_OFF - XH0_OFF)   // 36864
#define PAD (PA1_OFF - PA0_OFF)   // 9216

__device__ float g_S1p[2][Nn][Kk][Dd];
__device__ float g_S2p[2][Nn][Kk];

static __device__ __forceinline__ uint32_t smem_u32(const void* p) {
    uint32_t a;
    asm("{ .reg .u64 t; cvta.to.shared.u64 t, %1; cvt.u32.u64 %0, t; }" : "=r"(a) : "l"(p));
    return a;
}
static __device__ __forceinline__ void ldsm4(uint32_t r[4], uint32_t a) {
    asm volatile("ldmatrix.sync.aligned.m8n8.x4.shared.b16 {%0,%1,%2,%3}, [%4];"
                 : "=r"(r[0]), "=r"(r[1]), "=r"(r[2]), "=r"(r[3]) : "r"(a));
}
static __device__ __forceinline__ void ldsm4t(uint32_t r[4], uint32_t a) {
    asm volatile("ldmatrix.sync.aligned.m8n8.x4.trans.shared.b16 {%0,%1,%2,%3}, [%4];"
                 : "=r"(r[0]), "=r"(r[1]), "=r"(r[2]), "=r"(r[3]) : "r"(a));
}
static __device__ __forceinline__ void mma_f16(float c[4], const uint32_t a[4],
                                               uint32_t b0, uint32_t b1) {
    asm volatile(
        "mma.sync.aligned.m16n8k16.row.col.f32.f16.f16.f32 "
        "{%0,%1,%2,%3},{%4,%5,%6,%7},{%8,%9},{%0,%1,%2,%3};"
        : "+f"(c[0]), "+f"(c[1]), "+f"(c[2]), "+f"(c[3])
        : "r"(a[0]), "r"(a[1]), "r"(a[2]), "r"(a[3]), "r"(b0), "r"(b1));
}
#define BAR_SYNC(id, cnt)   asm volatile("bar.sync %0, %1;"   :: "r"(id), "r"(cnt) : "memory")
#define BAR_ARRIVE(id, cnt) asm volatile("bar.arrive %0, %1;" :: "r"(id), "r"(cnt) : "memory")
#define CP_ASYNC16(dst, src) \
    asm volatile("cp.async.cg.shared.global [%0], [%1], 16;" :: "r"(dst), "l"(src) : "memory")
#define CP_COMMIT()  asm volatile("cp.async.commit_group;" ::: "memory")
#define CP_WAIT0()   asm volatile("cp.async.wait_group 0;" ::: "memory")

// named barrier ids:
// 1 = G1 internal, 7 = G2 internal
// 2/3 = XHfree par0/1, 4/5 = XHready par0/1, 8/9 = PAready par0/1

__global__ void netvlad_noop() {}

__global__ __launch_bounds__(NT, 1)
void netvlad_mma(const float* __restrict__ x, const float* __restrict__ w) {
    extern __shared__ char sm[];
    const uint32_t sb = smem_u32(sm);
    const int tid = threadIdx.x;
    const int lane = tid & 31;
    const int n  = blockIdx.x >> 1;
    const int hf = blockIdx.x & 1;

    float* Lsp = (float*)(sm + LS_OFF);
    float* RN  = (float*)(sm + RN_OFF);

    // ---- load W fp16 [k][d] pitch 264 halves (all 512 threads) ----
    for (int i = tid; i < Kk * Dd; i += NT) {
        int k = i >> 8, d = i & 255;
        *(__half*)(sm + WH_OFF + k * 528 + 2 * d) = __float2half_rn(w[i]);
    }

    const float* xn = x + (size_t)n * Dd * Ll + (size_t)hf * 2048;

    // ---- G2 issues cp.async for tile 0 ----
    if (tid >= 256) {
        const int t2 = tid - 256;
#pragma unroll 4
        for (int i = 0; i < 16; ++i) {
            int c = t2 + 256 * i;
            int d = c >> 4, p4 = c & 15;
            uint32_t dst = sb + XRAW_OFF + d * 272 + p4 * 16;
            const float* src = xn + (size_t)d * Ll + p4 * 4;
            CP_ASYNC16(dst, src);
        }
        CP_COMMIT();
    }
    __syncthreads();

    if (tid < 256) {
        // ============ G1: norm-reduce + GEMM1 + softmax ============
        const int wv = tid >> 5;
        const int p0 = (wv >> 1) * 16;
        const int k0 = (wv & 1) * 32;
        const int g  = lane >> 2;
        const int tg = lane & 3;
        const int pp = tid >> 2;       // softmax pixel
        const int sg = tid & 3;        // softmax subgroup

        const uint32_t aA1b = sb + XH0_OFF +
            ((lane & 7) + ((lane >> 4) << 3)) * 144 + (p0 + ((lane >> 3) & 1) * 8) * 2;
        const uint32_t aB1 = sb + WH_OFF + (k0 + (lane & 15)) * 528 + ((lane >> 4) << 4);

        for (int t = 0; t < NTILES; ++t) {
            const int par = t & 1;
            BAR_SYNC(4 + par, NT);          // XH[par] + nrm[par] ready
                                            // (also orders prev softmax Lsp reads
                                            //  before this tile's GEMM1 writes)

            // norm reduction (warps 0,1): 1024 partials per parity
            if (tid < 64) {
                const float* nr = (const float*)(sm + NRM_OFF) + par * 1024;
                float q = 0.0f;
#pragma unroll
                for (int i = 0; i < 16; ++i) q += nr[i * 64 + tid];
                float nx = fmaxf(sqrtf(q), 1e-12f);
                ((float*)(sm + NX_OFF))[par * 64 + tid] = nx;
                RN[par * 64 + tid] = 1.0f / nx;
            }

            // GEMM1: logits_raw[p][k] = x^T W^T  (contraction d=256)
            {
                float l0[4] = {0, 0, 0, 0}, l1[4] = {0, 0, 0, 0};
                float l2[4] = {0, 0, 0, 0}, l3[4] = {0, 0, 0, 0};
                const uint32_t a1 = aA1b + (par ? XHD : 0);
#pragma unroll 4
                for (int ks = 0; ks < 16; ++ks) {
                    uint32_t A[4], B0[4], B1[4];
                    ldsm4t(A, a1 + ks * 2304);
                    ldsm4(B0, aB1 + ks * 32);
                    ldsm4(B1, aB1 + 16 * 528 + ks * 32);
                    mma_f16(l0, A, B0[0], B0[2]);
                    mma_f16(l1, A, B0[1], B0[3]);
                    mma_f16(l2, A, B1[0], B1[2]);
                    mma_f16(l3, A, B1[1], B1[3]);
                }
                int r0 = (p0 + g) * 68, r1 = (p0 + 8 + g) * 68;
                *(float2*)&Lsp[r0 + k0 + tg * 2]      = make_float2(l0[0], l0[1]);
                *(float2*)&Lsp[r1 + k0 + tg * 2]      = make_float2(l0[2], l0[3]);
                *(float2*)&Lsp[r0 + k0 + 8 + tg * 2]  = make_float2(l1[0], l1[1]);
                *(float2*)&Lsp[r1 + k0 + 8 + tg * 2]  = make_float2(l1[2], l1[3]);
                *(float2*)&Lsp[r0 + k0 + 16 + tg * 2] = make_float2(l2[0], l2[1]);
                *(float2*)&Lsp[r1 + k0 + 16 + tg * 2] = make_float2(l2[2], l2[3]);
                *(float2*)&Lsp[r0 + k0 + 24 + tg * 2] = make_float2(l3[0], l3[1]);
                *(float2*)&Lsp[r1 + k0 + 24 + tg * 2] = make_float2(l3[2], l3[3]);
            }
            BAR_ARRIVE(2 + par, NT);        // XH[par] reads done -> G2 may overwrite
            BAR_SYNC(1, 256);               // logits + RN visible within G1

            // softmax over k (4 threads per pixel), write probs*ri fp16
            // PA layout: [p][k] pitch 144B -> 2x STS.128 per thread
            {
                const float ri = RN[par * 64 + pp];
                const float* row = Lsp + pp * 68 + sg * 16;
                float e[16];
                float4 v0 = *(const float4*)(row + 0);
                float4 v1 = *(const float4*)(row + 4);
                float4 v2 = *(const float4*)(row + 8);
                float4 v3 = *(const float4*)(row + 12);
                e[0]=v0.x; e[1]=v0.y; e[2]=v0.z; e[3]=v0.w;
                e[4]=v1.x; e[5]=v1.y; e[6]=v1.z; e[7]=v1.w;
                e[8]=v2.x; e[9]=v2.y; e[10]=v2.z; e[11]=v2.w;
                e[12]=v3.x; e[13]=v3.y; e[14]=v3.z; e[15]=v3.w;
                float m = e[0];
#pragma unroll
                for (int j = 1; j < 16; ++j) m = fmaxf(m, e[j]);
                m = fmaxf(m, __shfl_xor_sync(0xffffffffu, m, 1));
                m = fmaxf(m, __shfl_xor_sync(0xffffffffu, m, 2));
                float ssum = 0.0f;
#pragma unroll
                for (int j = 0; j < 16; ++j) { e[j] = __expf(ri * (e[j] - m)); ssum += e[j]; }
                ssum += __shfl_xor_sync(0xffffffffu, ssum, 1);
                ssum += __shfl_xor_sync(0xffffffffu, ssum, 2);
                float sc = ri / ssum;
                uint32_t hb[8];
#pragma unroll
                for (int j = 0; j < 8; ++j) {
                    __half2 hv = __floats2half2_rn(e[2 * j] * sc, e[2 * j + 1] * sc);
                    hb[j] = *(uint32_t*)&hv;
                }
                char* pd = sm + (par ? PA1_OFF : PA0_OFF) + pp * 144 + sg * 32;
                *(uint4*)pd        = make_uint4(hb[0], hb[1], hb[2], hb[3]);
                *(uint4*)(pd + 16) = make_uint4(hb[4], hb[5], hb[6], hb[7]);
            }
            BAR_ARRIVE(8 + par, NT);        // PA[par] ready
            // trailing G1 barrier removed: loop-head BAR_SYNC(4+par^1, NT)
            // already orders these Lsp reads before next GEMM1's Lsp writes
        }
    } else {
        // ============ G2: convert + cp.async + GEMM2 + S2 ============
        const int t2 = tid - 256;
        const int pq4  = t2 & 15;      // pixel quad: p = 4*pq4 .. +3
        const int dq16 = t2 >> 4;      // 0..15, d-range dq16*16..+15
        const int d0 = ((t2 >> 5) >> 1) * 64;
        const int kq = ((t2 >> 5) & 1) * 32;
        const int g  = lane >> 2;
        const int tg = lane & 3;
        const int kS2 = t2 & 63;       // S2: fixed cluster per thread
        const int pgS2 = t2 >> 6;      // S2: pixel group (16 pixels)

        const uint32_t aA2b = sb + XH0_OFF + (d0 + (lane & 15)) * 144 + ((lane >> 4) << 4);
        // B from PA [p][k] via ldsm.trans (same address form as GEMM1's A operand)
        const uint32_t aB2b = sb + PA0_OFF +
            ((lane & 7) + ((lane >> 4) << 3)) * 144 + (kq + ((lane >> 3) & 1) * 8) * 2;

        float acc[4][4][4];
#pragma unroll
        for (int i = 0; i < 4; i++)
#pragma unroll
            for (int j = 0; j < 4; j++)
#pragma unroll
                for (int q = 0; q < 4; q++) acc[i][j][q] = 0.0f;
        float s2acc = 0.0f;

        for (int t = 0; t < NTILES; ++t) {
            const int par = t & 1;
            if (t >= 2) BAR_SYNC(2 + par, NT);   // XH[par] free
            CP_WAIT0();

            // convert XRAW -> fp16 XH[par]: 4 pixels x 16 d per thread (LDS.128/STS.64)
            {
                const char* srcb = sm + XRAW_OFF + pq4 * 16;
                char* dstb = sm + (par ? XH1_OFF : XH0_OFF) + pq4 * 8;
                float s0 = 0.0f, s1 = 0.0f, s2 = 0.0f, s3 = 0.0f;
#pragma unroll 8
                for (int j = 0; j < 16; ++j) {
                    int d = dq16 * 16 + j;
                    float4 v = *(const float4*)(srcb + d * 272);
                    s0 += v.x * v.x; s1 += v.y * v.y;
                    s2 += v.z * v.z; s3 += v.w * v.w;
                    __half2 h01 = __floats2half2_rn(v.x, v.y);
                    __half2 h23 = __floats2half2_rn(v.z, v.w);
                    *(uint2*)(dstb + d * 144) =
                        make_uint2(*(uint32_t*)&h01, *(uint32_t*)&h23);
                }
                float4* nr4 = (float4*)((float*)(sm + NRM_OFF) + par * 1024);
                nr4[dq16 * 16 + pq4] = make_float4(s0, s1, s2, s3);
            }
            BAR_SYNC(7, 256);                    // all XRAW reads done

            if (t + 1 < NTILES) {
#pragma unroll 4
                for (int i = 0; i < 16; ++i) {
                    int c = t2 + 256 * i;
                    int d = c >> 4, p4 = c & 15;
                    uint32_t dst = sb + XRAW_OFF + d * 272 + p4 * 16;
                    const float* src = xn + (size_t)d * Ll + (t + 1) * 64 + p4 * 4;
                    CP_ASYNC16(dst, src);
                }
                CP_COMMIT();
            }
            BAR_ARRIVE(4 + par, NT);             // XH[par] + nrm[par] ready

            if (t > 0) {
                const int q = par ^ 1;
                BAR_SYNC(8 + q, NT);             // PA[q] ready
                const uint32_t a2 = aA2b + (q ? XHD : 0);
                const uint32_t b2 = aB2b + (q ? PAD : 0);
#pragma unroll
                for (int ps = 0; ps < 4; ++ps) {
                    uint32_t B0[4], B1[4];
                    ldsm4t(B0, b2 + ps * 2304);
                    ldsm4t(B1, b2 + 32 + ps * 2304);
#pragma unroll
                    for (int i = 0; i < 4; ++i) {
                        uint32_t A[4];
                        ldsm4(A, a2 + i * 2304 + ps * 32);
                        mma_f16(acc[i][0], A, B0[0], B0[2]);
                        mma_f16(acc[i][1], A, B0[1], B0[3]);
                        mma_f16(acc[i][2], A, B1[0], B1[2]);
                        mma_f16(acc[i][3], A, B1[1], B1[3]);
                    }
                }
                // S2[k] += sum_p (probs*ri)[p][k] * ||x||[p]  (scalar per thread)
                {
                    const char* pab = sm + (q ? PA1_OFF : PA0_OFF) + 2 * kS2;
                    const float* nx = (const float*)(sm + NX_OFF) + q * 64 + pgS2 * 16;
#pragma unroll
                    for (int j = 0; j < 16; ++j) {
                        __half v = *(const __half*)(pab + (pgS2 * 16 + j) * 144);
                        s2acc += __half2float(v) * nx[j];
                    }
                }
            }
        }

        // tail: GEMM2 + S2 for tile 31 (par 1)
        {
            BAR_SYNC(9, NT);
            const uint32_t a2 = aA2b + XHD;
            const uint32_t b2 = aB2b + PAD;
#pragma unroll
            for (int ps = 0; ps < 4; ++ps) {
                uint32_t B0[4], B1[4];
                ldsm4t(B0, b2 + ps * 2304);
                ldsm4t(B1, b2 + 32 + ps * 2304);
#pragma unroll
                for (int i = 0; i < 4; ++i) {
                    uint32_t A[4];
                    ldsm4(A, a2 + i * 2304 + ps * 32);
                    mma_f16(acc[i][0], A, B0[0], B0[2]);
                    mma_f16(acc[i][1], A, B0[1], B0[3]);
                    mma_f16(acc[i][2], A, B1[0], B1[2]);
                    mma_f16(acc[i][3], A, B1[1], B1[3]);
                }
            }
            {
                const char* pab = sm + PA1_OFF + 2 * kS2;
                const float* nx = (const float*)(sm + NX_OFF) + 64 + pgS2 * 16;
#pragma unroll
                for (int j = 0; j < 16; ++j) {
                    __half v = *(const __half*)(pab + (pgS2 * 16 + j) * 144);
                    s2acc += __half2float(v) * nx[j];
                }
            }
        }
        // stage S2 partials (NRM region is dead now: G1 is past all nrm reads)
        ((float*)(sm + NRM_OFF))[pgS2 * 64 + kS2] = s2acc;

        // stage acc into XRAW region (only G2 touches XRAW)
        float* stg = (float*)sm;   // [64 k][260 d] f32
#pragma unroll
        for (int i = 0; i < 4; ++i)
#pragma unroll
            for (int j = 0; j < 4; ++j) {
                int d  = d0 + 16 * i + g;
                int kk = kq + 8 * j + tg * 2;
                stg[kk * 260 + d]           = acc[i][j][0];
                stg[(kk + 1) * 260 + d]     = acc[i][j][1];
                stg[kk * 260 + d + 8]       = acc[i][j][2];
                stg[(kk + 1) * 260 + d + 8] = acc[i][j][3];
            }
    }

    __syncthreads();   // staging complete (S1 + S2 partials)
    if (tid < 64) {
        const float* s2p = (const float*)(sm + NRM_OFF);
        g_S2p[hf][n][tid] = s2p[tid] + s2p[tid + 64] + s2p[tid + 128] + s2p[tid + 192];
    }
    {
        int k   = tid >> 3;
        int dq2 = (tid & 7) * 32;
        const float* stg = (const float*)sm;
#pragma unroll
        for (int jj = 0; jj < 8; ++jj) {
            float4 v = *(const float4*)&stg[k * 260 + dq2 + jj * 4];
            *(float4*)&g_S1p[hf][n][k][dq2 + jj * 4] = v;
        }
    }
}

__global__ __launch_bounds__(256)
void netvlad_finalize(const float* __restrict__ cent, float* __restrict__ out) {
    const int n = blockIdx.x;
    const int tid = threadIdx.x;
    const int w8 = tid >> 5, lane = tid & 31;
    __shared__ float s2s[64];
    __shared__ float wsum[8];
    __shared__ float ginv_s;

    if (tid < 64) s2s[tid] = g_S2p[0][n][tid] + g_S2p[1][n][tid];
    __syncthreads();

    float v[8][8];
    float gs = 0.0f;
#pragma unroll
    for (int kk = 0; kk < 8; ++kk) {
        int k = w8 * 8 + kk;
        float s2 = s2s[k];
        float loc = 0.0f;
#pragma unroll
        for (int j = 0; j < 8; ++j) {
            int d = j * 32 + lane;
            float a = g_S1p[0][n][k][d] + g_S1p[1][n][k][d] - s2 * cent[k * Dd + d];
            v[kk][j] = a;
            loc += a * a;
        }
#pragma unroll
        for (int o = 16; o > 0; o >>= 1) loc += __shfl_xor_sync(0xffffffffu, loc, o);
        float inv = 1.0f / fmaxf(sqrtf(loc), 1e-12f);
#pragma unroll
        for (int j = 0; j < 8; ++j) { v[kk][j] *= inv; gs += v[kk][j] * v[kk][j]; }
    }
#pragma unroll
    for (int o = 16; o > 0; o >>= 1) gs += __shfl_xor_sync(0xffffffffu, gs, o);
    if (lane == 0) wsum[w8] = gs;
    __syncthreads();
    if (tid == 0) {
        float t = 0.0f;
#pragma unroll
        for (int i = 0; i < 8; ++i) t += wsum[i];
        ginv_s = 1.0f / fmaxf(sqrtf(t), 1e-12f);
    }
    __syncthreads();
    float gi = ginv_s;
    size_t base = (size_t)n * Kk * Dd;
#pragma unroll
    for (int kk = 0; kk < 8; ++kk) {
        int k = w8 * 8 + kk;
#pragma unroll
        for (int j = 0; j < 8; ++j)
            out[base + (size_t)k * Dd + j * 32 + lane] = v[kk][j] * gi;
    }
}

extern "C" void kernel_launch(void* const* d_in, const int* in_sizes, int n_in,
                              void* d_out, int out_size) {
    const float* x = (const float*)d_in[0];
    const float* w = (const float*)d_in[1];
    const float* c = (const float*)d_in[2];
    float* out = (float*)d_out;

    cudaFuncSetAttribute(netvlad_mma,
                         cudaFuncAttributeMaxDynamicSharedMemorySize, SMEM_TOTAL);

    // 3-launch pattern keeps ncu (-s 5 -c 1) on netvlad_mma.
    netvlad_mma<<<2 * Nn, NT, SMEM_TOTAL>>>(x, w);
    netvlad_finalize<<<Nn, 256>>>(c, out);
    netvlad_noop<<<1, 32>>>();
}

// round 17
// speedup vs baseline: 1.5475x; 1.0166x over previous
#include <cuda_runtime.h>
#include <cuda_fp16.h>
#include <cstdint>
#include <math.h>

#define Nn 64
#define Kk 64
#define Dd 256
#define Ll 4096
#define NTILES 32
#define NT 512

// ---- smem byte offsets ----
#define XRAW_OFF 0        // raw x fp32 [256 d][68 p] (pitch 272B)
#define XH0_OFF  69632    // x fp16 [256 d][72 p] (pitch 144B), parity 0
#define XH1_OFF  106496   // parity 1
#define WH_OFF   143360   // W fp16 [64 k][264 d] (pitch 528B)
#define PA0_OFF  177152   // probs*ri fp16 [64 p][72 k] (pitch 144B), parity 0
#define PA1_OFF  186368   // parity 1
#define LS_OFF   195584   // logits [64 p][68 k] f32 (pitch 272B)
#define NRM_OFF  212992   // float[2][1024] partial sumsq (parity stride 1024)
#define RN_OFF   221184   // float[2][64]  ri = 1/||x||
#define NX_OFF   221696   // float[2][64]  ||x||
#define SMEM_TOTAL 222208

#define XHD (XH1_OFF - XH0_OFF)   // 36864
#define PAD (PA1_OFF - PA0_OFF)   // 9216

__device__ float g_S1p[2][Nn][Kk][Dd];
__device__ float g_S2p[2][Nn][Kk];

static __device__ __forceinline__ uint32_t smem_u32(const void* p) {
    uint32_t a;
    asm("{ .reg .u64 t; cvta.to.shared.u64 t, %1; cvt.u32.u64 %0, t; }" : "=r"(a) : "l"(p));
    return a;
}
static __device__ __forceinline__ void ldsm4(uint32_t r[4], uint32_t a) {
    asm volatile("ldmatrix.sync.aligned.m8n8.x4.shared.b16 {%0,%1,%2,%3}, [%4];"
                 : "=r"(r[0]), "=r"(r[1]), "=r"(r[2]), "=r"(r[3]) : "r"(a));
}
static __device__ __forceinline__ void ldsm4t(uint32_t r[4], uint32_t a) {
    asm volatile("ldmatrix.sync.aligned.m8n8.x4.trans.shared.b16 {%0,%1,%2,%3}, [%4];"
                 : "=r"(r[0]), "=r"(r[1]), "=r"(r[2]), "=r"(r[3]) : "r"(a));
}
static __device__ __forceinline__ void mma_f16(float c[4], const uint32_t a[4],
                                               uint32_t b0, uint32_t b1) {
    asm volatile(
        "mma.sync.aligned.m16n8k16.row.col.f32.f16.f16.f32 "
        "{%0,%1,%2,%3},{%4,%5,%6,%7},{%8,%9},{%0,%1,%2,%3};"
        : "+f"(c[0]), "+f"(c[1]), "+f"(c[2]), "+f"(c[3])
        : "r"(a[0]), "r"(a[1]), "r"(a[2]), "r"(a[3]), "r"(b0), "r"(b1));
}
#define BAR_SYNC(id, cnt)   asm volatile("bar.sync %0, %1;"   :: "r"(id), "r"(cnt) : "memory")
#define BAR_ARRIVE(id, cnt) asm volatile("bar.arrive %0, %1;" :: "r"(id), "r"(cnt) : "memory")
#define CP_ASYNC16(dst, src) \
    asm volatile("cp.async.cg.shared.global [%0], [%1], 16;" :: "r"(dst), "l"(src) : "memory")
#define CP_COMMIT()  asm volatile("cp.async.commit_group;" ::: "memory")
#define CP_WAIT0()   asm volatile("cp.async.wait_group 0;" ::: "memory")

// named barrier ids:
// 1 = G1 internal, 7 = G2 internal
// 2/3 = XHfree par0/1, 4/5 = XHready par0/1, 8/9 = PAready par0/1

__global__ void netvlad_noop() {}

__global__ __launch_bounds__(NT, 1)
void netvlad_mma(const float* __restrict__ x, const float* __restrict__ w) {
    extern __shared__ char sm[];
    const uint32_t sb = smem_u32(sm);
    const int tid = threadIdx.x;
    const int lane = tid & 31;
    const int n  = blockIdx.x >> 1;
    const int hf = blockIdx.x & 1;

    float* Lsp = (float*)(sm + LS_OFF);
    float* RN  = (float*)(sm + RN_OFF);

    // ---- load W fp16 [k][d] pitch 264 halves (all 512 threads) ----
    for (int i = tid; i < Kk * Dd; i += NT) {
        int k = i >> 8, d = i & 255;
        *(__half*)(sm + WH_OFF + k * 528 + 2 * d) = __float2half_rn(w[i]);
    }

    const float* xn = x + (size_t)n * Dd * Ll + (size_t)hf * 2048;

    // ---- G2 issues cp.async for tile 0 ----
    if (tid >= 256) {
        const int t2 = tid - 256;
#pragma unroll 4
        for (int i = 0; i < 16; ++i) {
            int c = t2 + 256 * i;
            int d = c >> 4, p4 = c & 15;
            uint32_t dst = sb + XRAW_OFF + d * 272 + p4 * 16;
            const float* src = xn + (size_t)d * Ll + p4 * 4;
            CP_ASYNC16(dst, src);
        }
        CP_COMMIT();
    }
    __syncthreads();

    if (tid < 256) {
        // ============ G1: norm-reduce + GEMM1 + softmax ============
        const int wv = tid >> 5;
        const int p0 = (wv >> 1) * 16;
        const int k0 = (wv & 1) * 32;
        const int g  = lane >> 2;
        const int tg = lane & 3;
        const int pp = tid >> 2;       // softmax pixel
        const int sg = tid & 3;        // softmax subgroup

        const uint32_t aA1b = sb + XH0_OFF +
            ((lane & 7) + ((lane >> 4) << 3)) * 144 + (p0 + ((lane >> 3) & 1) * 8) * 2;
        const uint32_t aB1 = sb + WH_OFF + (k0 + (lane & 15)) * 528 + ((lane >> 4) << 4);

        for (int t = 0; t < NTILES; ++t) {
            const int par = t & 1;
            BAR_SYNC(4 + par, NT);          // XH[par] + nrm[par] ready
                                            // (also orders prev softmax Lsp reads
                                            //  before this tile's GEMM1 writes)

            // norm reduction (warps 0,1): 1024 partials per parity
            if (tid < 64) {
                const float* nr = (const float*)(sm + NRM_OFF) + par * 1024;
                float q = 0.0f;
#pragma unroll
                for (int i = 0; i < 16; ++i) q += nr[i * 64 + tid];
                float nx = fmaxf(sqrtf(q), 1e-12f);
                ((float*)(sm + NX_OFF))[par * 64 + tid] = nx;
                RN[par * 64 + tid] = 1.0f / nx;
            }

            // GEMM1: logits_raw[p][k] = x^T W^T  (contraction d=256)
            {
                float l0[4] = {0, 0, 0, 0}, l1[4] = {0, 0, 0, 0};
                float l2[4] = {0, 0, 0, 0}, l3[4] = {0, 0, 0, 0};
                const uint32_t a1 = aA1b + (par ? XHD : 0);
#pragma unroll 4
                for (int ks = 0; ks < 16; ++ks) {
                    uint32_t A[4], B0[4], B1[4];
                    ldsm4t(A, a1 + ks * 2304);
                    ldsm4(B0, aB1 + ks * 32);
                    ldsm4(B1, aB1 + 16 * 528 + ks * 32);
                    mma_f16(l0, A, B0[0], B0[2]);
                    mma_f16(l1, A, B0[1], B0[3]);
                    mma_f16(l2, A, B1[0], B1[2]);
                    mma_f16(l3, A, B1[1], B1[3]);
                }
                int r0 = (p0 + g) * 68, r1 = (p0 + 8 + g) * 68;
                *(float2*)&Lsp[r0 + k0 + tg * 2]      = make_float2(l0[0], l0[1]);
                *(float2*)&Lsp[r1 + k0 + tg * 2]      = make_float2(l0[2], l0[3]);
                *(float2*)&Lsp[r0 + k0 + 8 + tg * 2]  = make_float2(l1[0], l1[1]);
                *(float2*)&Lsp[r1 + k0 + 8 + tg * 2]  = make_float2(l1[2], l1[3]);
                *(float2*)&Lsp[r0 + k0 + 16 + tg * 2] = make_float2(l2[0], l2[1]);
                *(float2*)&Lsp[r1 + k0 + 16 + tg * 2] = make_float2(l2[2], l2[3]);
                *(float2*)&Lsp[r0 + k0 + 24 + tg * 2] = make_float2(l3[0], l3[1]);
                *(float2*)&Lsp[r1 + k0 + 24 + tg * 2] = make_float2(l3[2], l3[3]);
            }
            BAR_ARRIVE(2 + par, NT);        // XH[par] reads done -> G2 may overwrite
            BAR_SYNC(1, 256);               // logits + RN visible within G1

            // softmax over k (4 threads per pixel), write probs*ri fp16
            // PA layout: [p][k] pitch 144B -> 2x STS.128 per thread
            {
                const float ri = RN[par * 64 + pp];
                const float* row = Lsp + pp * 68 + sg * 16;
                float e[16];
                float4 v0 = *(const float4*)(row + 0);
                float4 v1 = *(const float4*)(row + 4);
                float4 v2 = *(const float4*)(row + 8);
                float4 v3 = *(const float4*)(row + 12);
                e[0]=v0.x; e[1]=v0.y; e[2]=v0.z; e[3]=v0.w;
                e[4]=v1.x; e[5]=v1.y; e[6]=v1.z; e[7]=v1.w;
                e[8]=v2.x; e[9]=v2.y; e[10]=v2.z; e[11]=v2.w;
                e[12]=v3.x; e[13]=v3.y; e[14]=v3.z; e[15]=v3.w;
                float m = e[0];
#pragma unroll
                for (int j = 1; j < 16; ++j) m = fmaxf(m, e[j]);
                m = fmaxf(m, __shfl_xor_sync(0xffffffffu, m, 1));
                m = fmaxf(m, __shfl_xor_sync(0xffffffffu, m, 2));
                float ssum = 0.0f;
#pragma unroll
                for (int j = 0; j < 16; ++j) { e[j] = __expf(ri * (e[j] - m)); ssum += e[j]; }
                ssum += __shfl_xor_sync(0xffffffffu, ssum, 1);
                ssum += __shfl_xor_sync(0xffffffffu, ssum, 2);
                float sc = ri / ssum;
                uint32_t hb[8];
#pragma unroll
                for (int j = 0; j < 8; ++j) {
                    __half2 hv = __floats2half2_rn(e[2 * j] * sc, e[2 * j + 1] * sc);
                    hb[j] = *(uint32_t*)&hv;
                }
                char* pd = sm + (par ? PA1_OFF : PA0_OFF) + pp * 144 + sg * 32;
                *(uint4*)pd        = make_uint4(hb[0], hb[1], hb[2], hb[3]);
                *(uint4*)(pd + 16) = make_uint4(hb[4], hb[5], hb[6], hb[7]);
            }
            BAR_ARRIVE(8 + par, NT);        // PA[par] ready
        }
    } else {
        // ============ G2: convert + cp.async + GEMM2 + S2 ============
        const int t2 = tid - 256;
        const int pq4  = t2 & 15;      // pixel quad: p = 4*pq4 .. +3
        const int dq16 = t2 >> 4;      // 0..15, d-range dq16*16..+15
        const int d0 = ((t2 >> 5) >> 1) * 64;
        const int kq = ((t2 >> 5) & 1) * 32;
        const int g  = lane >> 2;
        const int tg = lane & 3;
        const int kS2 = t2 & 63;       // S2: fixed cluster per thread
        const int pgS2 = t2 >> 6;      // S2: pixel group (16 pixels)

        const uint32_t aA2b = sb + XH0_OFF + (d0 + (lane & 15)) * 144 + ((lane >> 4) << 4);
        // B from PA [p][k] via ldsm.trans (same address form as GEMM1's A operand)
        const uint32_t aB2b = sb + PA0_OFF +
            ((lane & 7) + ((lane >> 4) << 3)) * 144 + (kq + ((lane >> 3) & 1) * 8) * 2;

        float acc[4][4][4];
#pragma unroll
        for (int i = 0; i < 4; i++)
#pragma unroll
            for (int j = 0; j < 4; j++)
#pragma unroll
                for (int q = 0; q < 4; q++) acc[i][j][q] = 0.0f;
        float s2acc = 0.0f;

        for (int t = 0; t < NTILES; ++t) {
            const int par = t & 1;
            if (t >= 2) BAR_SYNC(2 + par, NT);   // XH[par] free
            CP_WAIT0();

            // convert XRAW -> fp16 XH[par]: 4 pixels x 16 d per thread (LDS.128/STS.64)
            {
                const char* srcb = sm + XRAW_OFF + pq4 * 16;
                char* dstb = sm + (par ? XH1_OFF : XH0_OFF) + pq4 * 8;
                float s0 = 0.0f, s1 = 0.0f, s2 = 0.0f, s3 = 0.0f;
#pragma unroll 8
                for (int j = 0; j < 16; ++j) {
                    int d = dq16 * 16 + j;
                    float4 v = *(const float4*)(srcb + d * 272);
                    s0 += v.x * v.x; s1 += v.y * v.y;
                    s2 += v.z * v.z; s3 += v.w * v.w;
                    __half2 h01 = __floats2half2_rn(v.x, v.y);
                    __half2 h23 = __floats2half2_rn(v.z, v.w);
                    *(uint2*)(dstb + d * 144) =
                        make_uint2(*(uint32_t*)&h01, *(uint32_t*)&h23);
                }
                float4* nr4 = (float4*)((float*)(sm + NRM_OFF) + par * 1024);
                nr4[dq16 * 16 + pq4] = make_float4(s0, s1, s2, s3);
            }
            BAR_SYNC(7, 256);                    // all XRAW reads done

            if (t + 1 < NTILES) {
#pragma unroll 4
                for (int i = 0; i < 16; ++i) {
                    int c = t2 + 256 * i;
                    int d = c >> 4, p4 = c & 15;
                    uint32_t dst = sb + XRAW_OFF + d * 272 + p4 * 16;
                    const float* src = xn + (size_t)d * Ll + (t + 1) * 64 + p4 * 4;
                    CP_ASYNC16(dst, src);
                }
                CP_COMMIT();
            }
            BAR_ARRIVE(4 + par, NT);             // XH[par] + nrm[par] ready

            if (t > 0) {
                const int q = par ^ 1;
                BAR_SYNC(8 + q, NT);             // PA[q] ready
                const uint32_t a2 = aA2b + (q ? XHD : 0);
                const uint32_t b2 = aB2b + (q ? PAD : 0);
#pragma unroll
                for (int ps = 0; ps < 4; ++ps) {
                    uint32_t B0[4], B1[4];
                    ldsm4t(B0, b2 + ps * 2304);
                    ldsm4t(B1, b2 + 32 + ps * 2304);
#pragma unroll
                    for (int i = 0; i < 4; ++i) {
                        uint32_t A[4];
                        ldsm4(A, a2 + i * 2304 + ps * 32);
                        mma_f16(acc[i][0], A, B0[0], B0[2]);
                        mma_f16(acc[i][1], A, B0[1], B0[3]);
                        mma_f16(acc[i][2], A, B1[0], B1[2]);
                        mma_f16(acc[i][3], A, B1[1], B1[3]);
                    }
                }
                // S2[k] += sum_p (probs*ri)[p][k] * ||x||[p]  (scalar per thread)
                {
                    const char* pab = sm + (q ? PA1_OFF : PA0_OFF) + 2 * kS2;
                    const float* nx = (const float*)(sm + NX_OFF) + q * 64 + pgS2 * 16;
#pragma unroll
                    for (int j = 0; j < 16; ++j) {
                        __half v = *(const __half*)(pab + (pgS2 * 16 + j) * 144);
                        s2acc += __half2float(v) * nx[j];
                    }
                }
            }
        }

        // tail: GEMM2 + S2 for tile 31 (par 1)
        {
            BAR_SYNC(9, NT);
            const uint32_t a2 = aA2b + XHD;
            const uint32_t b2 = aB2b + PAD;
#pragma unroll
            for (int ps = 0; ps < 4; ++ps) {
                uint32_t B0[4], B1[4];
                ldsm4t(B0, b2 + ps * 2304);
                ldsm4t(B1, b2 + 32 + ps * 2304);
#pragma unroll
                for (int i = 0; i < 4; ++i) {
                    uint32_t A[4];
                    ldsm4(A, a2 + i * 2304 + ps * 32);
                    mma_f16(acc[i][0], A, B0[0], B0[2]);
                    mma_f16(acc[i][1], A, B0[1], B0[3]);
                    mma_f16(acc[i][2], A, B1[0], B1[2]);
                    mma_f16(acc[i][3], A, B1[1], B1[3]);
                }
            }
            {
                const char* pab = sm + PA1_OFF + 2 * kS2;
                const float* nx = (const float*)(sm + NX_OFF) + 64 + pgS2 * 16;
#pragma unroll
                for (int j = 0; j < 16; ++j) {
                    __half v = *(const __half*)(pab + (pgS2 * 16 + j) * 144);
                    s2acc += __half2float(v) * nx[j];
                }
            }
        }
        // stage S2 partials (NRM region is dead now: G1 is past all nrm reads)
        ((float*)(sm + NRM_OFF))[pgS2 * 64 + kS2] = s2acc;

        // stage acc into XRAW region (only G2 touches XRAW)
        float* stg = (float*)sm;   // [64 k][260 d] f32
#pragma unroll
        for (int i = 0; i < 4; ++i)
#pragma unroll
            for (int j = 0; j < 4; ++j) {
                int d  = d0 + 16 * i + g;
                int kk = kq + 8 * j + tg * 2;
                stg[kk * 260 + d]           = acc[i][j][0];
                stg[(kk + 1) * 260 + d]     = acc[i][j][1];
                stg[kk * 260 + d + 8]       = acc[i][j][2];
                stg[(kk + 1) * 260 + d + 8] = acc[i][j][3];
            }
    }

    __syncthreads();   // staging complete (S1 + S2 partials)
    if (tid < 64) {
        const float* s2p = (const float*)(sm + NRM_OFF);
        g_S2p[hf][n][tid] = s2p[tid] + s2p[tid + 64] + s2p[tid + 128] + s2p[tid + 192];
    }
    {
        int k   = tid >> 3;
        int dq2 = (tid & 7) * 32;
        const float* stg = (const float*)sm;
#pragma unroll
        for (int jj = 0; jj < 8; ++jj) {
            float4 v = *(const float4*)&stg[k * 260 + dq2 + jj * 4];
            *(float4*)&g_S1p[hf][n][k][dq2 + jj * 4] = v;
        }
    }
}

// 512-thread finalize: 16 warps, each owns 4 clusters (v[4][8] = 32 regs vs 64)
__global__ __launch_bounds__(512)
void netvlad_finalize(const float* __restrict__ cent, float* __restrict__ out) {
    const int n = blockIdx.x;
    const int tid = threadIdx.x;
    const int w16 = tid >> 5, lane = tid & 31;
    __shared__ float s2s[64];
    __shared__ float wsum[16];
    __shared__ float ginv_s;

    if (tid < 64) s2s[tid] = g_S2p[0][n][tid] + g_S2p[1][n][tid];
    __syncthreads();

    float v[4][8];
    float gs = 0.0f;
#pragma unroll
    for (int kk = 0; kk < 4; ++kk) {
        int k = w16 * 4 + kk;
        float s2 = s2s[k];
        float loc = 0.0f;
#pragma unroll
        for (int j = 0; j < 8; ++j) {
            int d = j * 32 + lane;
            float a = g_S1p[0][n][k][d] + g_S1p[1][n][k][d] - s2 * cent[k * Dd + d];
            v[kk][j] = a;
            loc += a * a;
        }
#pragma unroll
        for (int o = 16; o > 0; o >>= 1) loc += __shfl_xor_sync(0xffffffffu, loc, o);
        float inv = 1.0f / fmaxf(sqrtf(loc), 1e-12f);
#pragma unroll
        for (int j = 0; j < 8; ++j) { v[kk][j] *= inv; gs += v[kk][j] * v[kk][j]; }
    }
#pragma unroll
    for (int o = 16; o > 0; o >>= 1) gs += __shfl_xor_sync(0xffffffffu, gs, o);
    if (lane == 0) wsum[w16] = gs;
    __syncthreads();
    if (tid == 0) {
        float t = 0.0f;
#pragma unroll
        for (int i = 0; i < 16; ++i) t += wsum[i];
        ginv_s = 1.0f / fmaxf(sqrtf(t), 1e-12f);
    }
    __syncthreads();
    float gi = ginv_s;
    size_t base = (size_t)n * Kk * Dd;
#pragma unroll
    for (int kk = 0; kk < 4; ++kk) {
        int k = w16 * 4 + kk;
#pragma unroll
        for (int j = 0; j < 8; ++j)
            out[base + (size_t)k * Dd + j * 32 + lane] = v[kk][j] * gi;
    }
}

extern "C" void kernel_launch(void* const* d_in, const int* in_sizes, int n_in,
                              void* d_out, int out_size) {
    const float* x = (const float*)d_in[0];
    const float* w = (const float*)d_in[1];
    const float* c = (const float*)d_in[2];
    float* out = (float*)d_out;

    cudaFuncSetAttribute(netvlad_mma,
                         cudaFuncAttributeMaxDynamicSharedMemorySize, SMEM_TOTAL);

    // 3-launch pattern keeps ncu (-s 5 -c 1) on netvlad_mma.
    netvlad_mma<<<2 * Nn, NT, SMEM_TOTAL>>>(x, w);
    netvlad_finalize<<<Nn, 512>>>(c, out);
    netvlad_noop<<<1, 32>>>();
}